// round 2
// baseline (speedup 1.0000x reference)
#include <cuda_runtime.h>
#include <cuda_bf16.h>
#include <cstdint>

// Problem constants (fixed shapes per reference)
#define NUM_NODES 100000
#define NUM_EDGES 50000
#define NUM_CONN  800000
#define IN_DIM    256
#define HIDDEN    128
#define OUT_DIM   17
#define LN_EPS    1e-5f

// ---------------- scratch (static device globals; no allocation) ----------------
__device__ int   g_counts[NUM_EDGES];
__device__ int   g_offsets[NUM_EDGES + 1];
__device__ int   g_cursor[NUM_EDGES];
__device__ int   g_csr[NUM_CONN];
__device__ __align__(16) float g_edge_feat[(size_t)NUM_EDGES * IN_DIM];

// ---------------- K0: zero counts ----------------
__global__ void zero_counts_kernel() {
    int i = blockIdx.x * blockDim.x + threadIdx.x;
    if (i < NUM_EDGES) g_counts[i] = 0;
}

// ---------------- K1: histogram of edge ids (hyperedge_index is int32!) ----------------
__global__ void count_kernel(const int* __restrict__ he) {
    int c = blockIdx.x * blockDim.x + threadIdx.x;
    if (c < NUM_CONN) {
        int e = he[NUM_CONN + c];            // edges = second row
        if ((unsigned)e < NUM_EDGES) atomicAdd(&g_counts[e], 1);
    }
}

// ---------------- K2: exclusive scan (single block, shuffle-based) ----------------
__global__ void scan_kernel() {
    __shared__ int warp_pref[32];
    __shared__ int sh_carry;
    __shared__ int sh_chunk_total;
    int tid = threadIdx.x, lane = tid & 31, wid = tid >> 5;
    if (tid == 0) sh_carry = 0;
    __syncthreads();
    for (int base = 0; base < NUM_EDGES; base += 1024) {
        int i = base + tid;
        int v = (i < NUM_EDGES) ? g_counts[i] : 0;
        int x = v;
        #pragma unroll
        for (int off = 1; off < 32; off <<= 1) {
            int t = __shfl_up_sync(0xffffffffu, x, off);
            if (lane >= off) x += t;
        }
        if (lane == 31) warp_pref[wid] = x;
        __syncthreads();
        if (wid == 0) {
            int t = warp_pref[lane];
            int y = t;
            #pragma unroll
            for (int off = 1; off < 32; off <<= 1) {
                int u = __shfl_up_sync(0xffffffffu, y, off);
                if (lane >= off) y += u;
            }
            warp_pref[lane] = y - t;            // exclusive warp prefix
            if (lane == 31) sh_chunk_total = y; // total of chunk
        }
        __syncthreads();
        int excl = (x - v) + warp_pref[wid] + sh_carry;
        if (i < NUM_EDGES) {
            g_offsets[i] = excl;
            g_cursor[i]  = excl;
        }
        __syncthreads();
        if (tid == 0) sh_carry += sh_chunk_total;
        __syncthreads();
    }
    if (threadIdx.x == 0) g_offsets[NUM_EDGES] = sh_carry;
}

// ---------------- K3: fill CSR ----------------
__global__ void fill_kernel(const int* __restrict__ he) {
    int c = blockIdx.x * blockDim.x + threadIdx.x;
    if (c < NUM_CONN) {
        int e = he[NUM_CONN + c];
        if ((unsigned)e < NUM_EDGES) {
            int pos = atomicAdd(&g_cursor[e], 1);
            int n = he[c];                   // node id
            g_csr[pos] = ((unsigned)n < NUM_NODES) ? n : 0;
        }
    }
}

// ---------------- K4: warp-per-edge gather + mean ----------------
__global__ void aggregate_kernel(const float* __restrict__ nf) {
    int gw   = (blockIdx.x * blockDim.x + threadIdx.x) >> 5;
    int lane = threadIdx.x & 31;
    if (gw >= NUM_EDGES) return;
    int beg = g_offsets[gw];
    int end = g_offsets[gw + 1];
    float4 a0 = make_float4(0.f, 0.f, 0.f, 0.f);
    float4 a1 = make_float4(0.f, 0.f, 0.f, 0.f);
    for (int i = beg; i < end; i++) {
        int n = g_csr[i];
        const float4* row = (const float4*)(nf + (size_t)n * IN_DIM);
        float4 v0 = __ldg(&row[lane]);
        float4 v1 = __ldg(&row[32 + lane]);
        a0.x += v0.x; a0.y += v0.y; a0.z += v0.z; a0.w += v0.w;
        a1.x += v1.x; a1.y += v1.y; a1.z += v1.z; a1.w += v1.w;
    }
    int cnt = end - beg;
    float inv = 1.f / (float)(cnt > 0 ? cnt : 1);
    a0.x *= inv; a0.y *= inv; a0.z *= inv; a0.w *= inv;
    a1.x *= inv; a1.y *= inv; a1.z *= inv; a1.w *= inv;
    float4* dst = (float4*)(g_edge_feat + (size_t)gw * IN_DIM);
    dst[lane]      = a0;
    dst[32 + lane] = a1;
}

// ---------------- K5: fused GEMM1 + bias + LayerNorm + ReLU + GEMM2 + bias ----------------
// 128 threads, 25 rows per block (50000 / 25 = 2000 blocks, no tail).
// Thread tid owns output column j=tid of GEMM1 for all 25 rows.
#define ROWS 25
__global__ void __launch_bounds__(128) mlp_kernel(
    const float* __restrict__ W1, const float* __restrict__ b1,
    const float* __restrict__ lng, const float* __restrict__ lnb,
    const float* __restrict__ W2, const float* __restrict__ b2,
    float* __restrict__ out)
{
    __shared__ float Xs[ROWS][IN_DIM];       // 25*256*4 = 25600 B
    __shared__ float Hs[ROWS][HIDDEN];       // 25*128*4 = 12800 B
    __shared__ float W2s[HIDDEN * OUT_DIM];  // 8704 B
    __shared__ float b2s[OUT_DIM];

    int tid  = threadIdx.x;
    int row0 = blockIdx.x * ROWS;

    // load X tile (float4)
    for (int idx = tid; idx < ROWS * (IN_DIM / 4); idx += 128) {
        int r = idx / (IN_DIM / 4);
        int c = idx % (IN_DIM / 4);
        ((float4*)&Xs[r][0])[c] =
            ((const float4*)(g_edge_feat + (size_t)(row0 + r) * IN_DIM))[c];
    }
    for (int idx = tid; idx < HIDDEN * OUT_DIM; idx += 128) W2s[idx] = W2[idx];
    if (tid < OUT_DIM) b2s[tid] = b2[tid];
    __syncthreads();

    // GEMM1: acc[r] = sum_k Xs[r][k] * W1[k][tid]
    float acc[ROWS];
    #pragma unroll
    for (int r = 0; r < ROWS; r++) acc[r] = 0.f;

    for (int k = 0; k < IN_DIM; k += 4) {
        float w0 = W1[(k + 0) * HIDDEN + tid];
        float w1 = W1[(k + 1) * HIDDEN + tid];
        float w2 = W1[(k + 2) * HIDDEN + tid];
        float w3 = W1[(k + 3) * HIDDEN + tid];
        #pragma unroll
        for (int r = 0; r < ROWS; r++) {
            float4 x = *(const float4*)&Xs[r][k];  // broadcast LDS.128
            acc[r] = fmaf(x.x, w0, acc[r]);
            acc[r] = fmaf(x.y, w1, acc[r]);
            acc[r] = fmaf(x.z, w2, acc[r]);
            acc[r] = fmaf(x.w, w3, acc[r]);
        }
    }

    float b1v = b1[tid];
    #pragma unroll
    for (int r = 0; r < ROWS; r++) Hs[r][tid] = acc[r] + b1v;
    __syncthreads();

    // LayerNorm + ReLU, warp-per-row (4 warps stride over 25 rows)
    int wid = tid >> 5, lane = tid & 31;
    for (int r = wid; r < ROWS; r += 4) {
        float s = 0.f, s2 = 0.f;
        #pragma unroll
        for (int j = 0; j < 4; j++) {
            float v = Hs[r][lane + 32 * j];
            s += v; s2 += v * v;
        }
        #pragma unroll
        for (int o = 16; o; o >>= 1) {
            s  += __shfl_xor_sync(0xffffffffu, s, o);
            s2 += __shfl_xor_sync(0xffffffffu, s2, o);
        }
        float mu  = s * (1.f / HIDDEN);
        float var = s2 * (1.f / HIDDEN) - mu * mu;
        float rs  = rsqrtf(var + LN_EPS);
        #pragma unroll
        for (int j = 0; j < 4; j++) {
            int c = lane + 32 * j;
            float v = (Hs[r][c] - mu) * rs * lng[c] + lnb[c];
            Hs[r][c] = fmaxf(v, 0.f);
        }
    }
    __syncthreads();

    // GEMM2: out[r][o] = b2[o] + sum_j Hs[r][j] * W2[j][o]
    for (int idx = tid; idx < ROWS * OUT_DIM; idx += 128) {
        int r = idx / OUT_DIM, o = idx % OUT_DIM;
        float s = b2s[o];
        #pragma unroll 8
        for (int j = 0; j < HIDDEN; j++) s = fmaf(Hs[r][j], W2s[j * OUT_DIM + o], s);
        out[(size_t)(row0 + r) * OUT_DIM + o] = s;
    }
}

// ---------------- launch ----------------
extern "C" void kernel_launch(void* const* d_in, const int* in_sizes, int n_in,
                              void* d_out, int out_size)
{
    const float* node_features = (const float*)d_in[0];
    const int*   he            = (const int*)d_in[1];   // int32! (JAX x64 disabled)
    const float* W1            = (const float*)d_in[2];
    const float* b1            = (const float*)d_in[3];
    const float* ln_g          = (const float*)d_in[4];
    const float* ln_b          = (const float*)d_in[5];
    const float* W2            = (const float*)d_in[6];
    const float* b2            = (const float*)d_in[7];
    float*       out           = (float*)d_out;

    zero_counts_kernel<<<(NUM_EDGES + 255) / 256, 256>>>();
    count_kernel<<<(NUM_CONN + 255) / 256, 256>>>(he);
    scan_kernel<<<1, 1024>>>();
    fill_kernel<<<(NUM_CONN + 255) / 256, 256>>>(he);
    aggregate_kernel<<<(NUM_EDGES * 32 + 255) / 256, 256>>>(node_features);
    mlp_kernel<<<NUM_EDGES / ROWS, 128>>>(W1, b1, ln_g, ln_b, W2, b2, out);
}